// round 13
// baseline (speedup 1.0000x reference)
#include <cuda_runtime.h>
#include <math.h>

#define BATCH 4096
#define C1O 10
#define P1 31
#define FEAT 3920
#define GH 64
#define NE 8
#define HID 128
#define HID2 64
#define NOUT 1000

// ---------------- scratch ----------------
__device__ float g_p1max[(size_t)BATCH * C1O * P1 * P1];
__device__ float g_p1min[(size_t)BATCH * C1O * P1 * P1];
__device__ float g_feat[(size_t)BATCH * FEAT];
__device__ float g_gh[(size_t)BATCH * GH];
__device__ float g_h1[(size_t)BATCH * 2 * HID];
__device__ float g_h2[(size_t)BATCH * 2 * HID2];
__device__ float g_gatew[BATCH * 2];
__device__ int   g_list[NE * BATCH];
__device__ int   g_cnt[NE];
__device__ double g_sum[C1O], g_sumsq[C1O];
__device__ float g_bnA[C1O], g_bnB[C1O];

// ---------------- f32x2 helpers ----------------
__device__ __forceinline__ unsigned long long pack2(float lo, float hi) {
    unsigned long long r;
    asm("mov.b64 %0, {%1, %2};" : "=l"(r) : "f"(lo), "f"(hi));
    return r;
}
__device__ __forceinline__ void unpack2(unsigned long long v, float& lo, float& hi) {
    asm("mov.b64 {%0, %1}, %2;" : "=f"(lo), "=f"(hi) : "l"(v));
}
__device__ __forceinline__ unsigned long long fma2(unsigned long long a,
                                                   unsigned long long b,
                                                   unsigned long long c) {
    unsigned long long d;
    asm("fma.rn.f32x2 %0, %1, %2, %3;" : "=l"(d) : "l"(a), "l"(b), "l"(c));
    return d;
}

// ---------------- init ----------------
__global__ void init_kernel(float* out) {
    size_t stride = (size_t)gridDim.x * blockDim.x;
    for (size_t i = (size_t)blockIdx.x * blockDim.x + threadIdx.x;
         i < (size_t)BATCH * NOUT; i += stride)
        out[i] = 0.f;
    if (blockIdx.x == 0 && threadIdx.x < 32) {
        if (threadIdx.x < NE) g_cnt[threadIdx.x] = 0;
        if (threadIdx.x < C1O) { g_sum[threadIdx.x] = 0.0; g_sumsq[threadIdx.x] = 0.0; }
    }
}

// ---------------- conv1 (3->10,5x5,p1): R6 two row-passes ----------
__global__ __launch_bounds__(256, 2) void conv1_kernel(const float* __restrict__ x,
                                                       const float* __restrict__ w,
                                                       const float* __restrict__ b) {
    extern __shared__ float sm[];
    float* pin = sm;                           // [3][66][68] = 13464
    float2* ws2 = (float2*)(sm + 13464);       // 750 duplicated weights
    float* bs = sm + 13464 + 1500;             // 10
    __shared__ float sh1[C1O], sh2[C1O];
    const int n = blockIdx.x, tid = threadIdx.x;

    if (tid < C1O) { sh1[tid] = 0.f; sh2[tid] = 0.f; bs[tid] = b[tid]; }
    for (int i = tid; i < 13464; i += 256) pin[i] = 0.f;
    for (int i = tid; i < 750; i += 256) { float wv = w[i]; ws2[i] = make_float2(wv, wv); }
    __syncthreads();
    const float* xn = x + (size_t)n * 3 * 64 * 64;
    for (int i = tid; i < 3 * 64 * 64; i += 256) {
        int c = i >> 12, r = (i >> 6) & 63, cc = i & 63;
        pin[(c * 66 + r + 1) * 68 + cc + 1] = xn[i];
    }
    __syncthreads();

    const bool valid = tid < 248;
    const int i = valid ? (tid >> 3) : 30;
    const int xg = (tid & 7) << 3;

#pragma unroll 1
    for (int grp = 0; grp < 2; grp++) {
        const int co0 = grp * 5;
        float cmx[5][4], cmn[5][4];
        float s1[5], s2[5];
#pragma unroll
        for (int co = 0; co < 5; co++) { s1[co] = 0.f; s2[co] = 0.f; }

#pragma unroll 1
        for (int pass = 0; pass < 2; pass++) {
            const int y = 2 * i + pass;
            unsigned long long acc[5][4];
#pragma unroll
            for (int co = 0; co < 5; co++) {
                float bb = bs[co0 + co];
                unsigned long long bp = pack2(bb, bb);
#pragma unroll
                for (int p = 0; p < 4; p++) acc[co][p] = bp;
            }
#pragma unroll 1
            for (int ci = 0; ci < 3; ci++) {
                const float* rb = &pin[(ci * 66 + y) * 68 + xg];
#pragma unroll
                for (int ky = 0; ky < 5; ky++) {
                    const float* rp = rb + ky * 68;
                    float4 q0 = *(const float4*)rp;
                    float4 q1 = *(const float4*)(rp + 4);
                    float4 q2 = *(const float4*)(rp + 8);
                    unsigned long long pe[6] = {
                        pack2(q0.x, q0.y), pack2(q0.z, q0.w), pack2(q1.x, q1.y),
                        pack2(q1.z, q1.w), pack2(q2.x, q2.y), pack2(q2.z, q2.w)};
                    unsigned long long po[5] = {
                        pack2(q0.y, q0.z), pack2(q0.w, q1.x), pack2(q1.y, q1.z),
                        pack2(q1.w, q2.x), pack2(q2.y, q2.z)};
#pragma unroll
                    for (int co = 0; co < 5; co++) {
                        const float2* wb = &ws2[((co0 + co) * 3 + ci) * 25 + ky * 5];
#pragma unroll
                        for (int kx = 0; kx < 5; kx++) {
                            unsigned long long w2 = *(const unsigned long long*)(wb + kx);
#pragma unroll
                            for (int p = 0; p < 4; p++) {
                                unsigned long long in = (kx & 1) ? po[p + (kx >> 1)]
                                                                 : pe[p + (kx >> 1)];
                                acc[co][p] = fma2(in, w2, acc[co][p]);
                            }
                        }
                    }
                }
            }
            // fold pass: stats + horizontal pool
#pragma unroll
            for (int co = 0; co < 5; co++) {
                float v[8];
#pragma unroll
                for (int p = 0; p < 4; p++) unpack2(acc[co][p], v[2 * p], v[2 * p + 1]);
                if (valid) {
#pragma unroll
                    for (int j = 0; j < 8; j++)
                        if (xg + j < 62) { float t = v[j]; s1[co] += t; s2[co] += t * t; }
                }
#pragma unroll
                for (int p = 0; p < 4; p++) {
                    float hx = fmaxf(v[2 * p], v[2 * p + 1]);
                    float hn = fminf(v[2 * p], v[2 * p + 1]);
                    if (pass == 0) { cmx[co][p] = hx; cmn[co][p] = hn; }
                    else { cmx[co][p] = fmaxf(cmx[co][p], hx); cmn[co][p] = fminf(cmn[co][p], hn); }
                }
            }
        }

        // stats reduce + pooled store
#pragma unroll
        for (int co = 0; co < 5; co++) {
            float a1 = s1[co], a2 = s2[co];
#pragma unroll
            for (int off = 16; off > 0; off >>= 1) {
                a1 += __shfl_down_sync(0xffffffffu, a1, off);
                a2 += __shfl_down_sync(0xffffffffu, a2, off);
            }
            if ((tid & 31) == 0) { atomicAdd(&sh1[co0 + co], a1); atomicAdd(&sh2[co0 + co], a2); }
            if (valid) {
                size_t ob = (((size_t)n * C1O + co0 + co) * P1 + i) * P1;
                int pc0 = xg >> 1;
#pragma unroll
                for (int p = 0; p < 4; p++) {
                    int pc = pc0 + p;
                    if (pc < P1) {
                        g_p1max[ob + pc] = cmx[co][p];
                        g_p1min[ob + pc] = cmn[co][p];
                    }
                }
            }
        }
    }
    __syncthreads();
    if (tid < C1O) {
        atomicAdd(&g_sum[tid], (double)sh1[tid]);
        atomicAdd(&g_sumsq[tid], (double)sh2[tid]);
    }
}

// ---------------- BN finalize ----------------
__global__ void bn_finalize(const float* __restrict__ gg, const float* __restrict__ gb) {
    int c = threadIdx.x;
    if (c < C1O) {
        double cnt = (double)BATCH * 62.0 * 62.0;
        double mean = g_sum[c] / cnt;
        double var = g_sumsq[c] / cnt - mean * mean;
        float istd = (float)(1.0 / sqrt(var + 1e-5));
        float a = gg[c] * istd;
        g_bnA[c] = a;
        g_bnB[c] = gb[c] - (float)mean * a;
    }
}

// ---------------- conv2 (10->20,5x5,p1): R6 two row-passes ----------
__global__ __launch_bounds__(256, 2) void conv2_kernel(const float* __restrict__ w,
                                                       const float* __restrict__ b) {
    extern __shared__ float sm[];
    float* pin = sm;                          // [10][33][40] = 13200
    float2* ws2 = (float2*)(sm + 13200);      // 5000
    float* bs = sm + 13200 + 10000;           // 20
    const int n = blockIdx.x, tid = threadIdx.x;

    for (int i = tid; i < 13200; i += 256) pin[i] = 0.f;
    for (int i = tid; i < 5000; i += 256) { float wv = w[i]; ws2[i] = make_float2(wv, wv); }
    if (tid < 20) bs[tid] = b[tid];
    __syncthreads();

    const float* pmaxn = g_p1max + (size_t)n * C1O * P1 * P1;
    const float* pminn = g_p1min + (size_t)n * C1O * P1 * P1;
    for (int idx = tid; idx < C1O * P1 * P1; idx += 256) {
        int c = idx / 961;
        int r = (idx - c * 961) / 31;
        int cc = idx - c * 961 - r * 31;
        float a = g_bnA[c];
        float v = (a >= 0.f) ? pmaxn[idx] : pminn[idx];
        pin[(c * 33 + r + 1) * 40 + cc + 1] = fmaxf(fmaf(a, v, g_bnB[c]), 0.f);
    }
    __syncthreads();

    const int grp = tid >> 6;
    const int rem = tid & 63;
    const bool act = rem < 56;
    const int i2 = act ? (rem >> 2) : 0;
    const int jg = rem & 3;
    const int co0 = grp * 5, c0 = jg * 8;

    float carry[5][4];
#pragma unroll 1
    for (int pass = 0; pass < 2; pass++) {
        const int y = 2 * i2 + pass;
        unsigned long long acc[5][4];
#pragma unroll
        for (int co = 0; co < 5; co++) {
            float bb = bs[co0 + co];
            unsigned long long bp = pack2(bb, bb);
#pragma unroll
            for (int p = 0; p < 4; p++) acc[co][p] = bp;
        }
#pragma unroll 1
        for (int ci = 0; ci < 10; ci++) {
            const float* rb = &pin[(ci * 33 + y) * 40 + c0];
#pragma unroll
            for (int ky = 0; ky < 5; ky++) {
                const float* rp = rb + ky * 40;
                float4 q0 = *(const float4*)rp;
                float4 q1 = *(const float4*)(rp + 4);
                float4 q2 = *(const float4*)(rp + 8);
                unsigned long long pe[6] = {
                    pack2(q0.x, q0.y), pack2(q0.z, q0.w), pack2(q1.x, q1.y),
                    pack2(q1.z, q1.w), pack2(q2.x, q2.y), pack2(q2.z, q2.w)};
                unsigned long long po[5] = {
                    pack2(q0.y, q0.z), pack2(q0.w, q1.x), pack2(q1.y, q1.z),
                    pack2(q1.w, q2.x), pack2(q2.y, q2.z)};
#pragma unroll
                for (int co = 0; co < 5; co++) {
                    const float2* wb = &ws2[((co0 + co) * 10 + ci) * 25 + ky * 5];
#pragma unroll
                    for (int kx = 0; kx < 5; kx++) {
                        unsigned long long w2 = *(const unsigned long long*)(wb + kx);
#pragma unroll
                        for (int p = 0; p < 4; p++) {
                            unsigned long long in = (kx & 1) ? po[p + (kx >> 1)]
                                                             : pe[p + (kx >> 1)];
                            acc[co][p] = fma2(in, w2, acc[co][p]);
                        }
                    }
                }
            }
        }
#pragma unroll
        for (int co = 0; co < 5; co++) {
#pragma unroll
            for (int p = 0; p < 4; p++) {
                float lo, hi;
                unpack2(acc[co][p], lo, hi);
                float h = fmaxf(lo, hi);
                if (pass == 0) carry[co][p] = h;
                else carry[co][p] = fmaxf(carry[co][p], h);
            }
        }
    }

    if (act) {
#pragma unroll
        for (int co = 0; co < 5; co++) {
            size_t ob = (size_t)n * FEAT + (co0 + co) * 196 + i2 * 14;
#pragma unroll
            for (int p = 0; p < 4; p++) {
                int oc = jg * 4 + p;
                if (oc < 14) g_feat[ob + oc] = fmaxf(carry[co][p], 0.f);
            }
        }
    }
}

// ---------------- gate layer 2 + top-2 + list build ----------------
__global__ __launch_bounds__(256) void gate2_kernel(const float* __restrict__ w2,
                                                    const float* __restrict__ b2) {
    __shared__ float ws[NE * GH], bs[NE];
    int tid = threadIdx.x;
    for (int i = tid; i < NE * GH; i += 256) ws[i] = w2[i];
    if (tid < NE) bs[tid] = b2[tid];
    __syncthreads();

    int bsmp = blockIdx.x * 256 + tid;
    if (bsmp >= BATCH) return;
    float h[GH];
    const float* row = g_gh + (size_t)bsmp * GH;
#pragma unroll
    for (int i = 0; i < GH; i++) h[i] = row[i];

    float lg[NE];
#pragma unroll
    for (int e = 0; e < NE; e++) {
        float s = bs[e];
        const float* wr = &ws[e * GH];
#pragma unroll
        for (int i = 0; i < GH; i++) s = fmaf(h[i], wr[i], s);
        lg[e] = s;
    }
    int i0 = 0;
#pragma unroll
    for (int e = 1; e < NE; e++) if (lg[e] > lg[i0]) i0 = e;
    int i1 = (i0 == 0) ? 1 : 0;
#pragma unroll
    for (int e = 0; e < NE; e++) if (e != i0 && lg[e] > lg[i1]) i1 = e;
    float w0 = 1.f / (1.f + expf(lg[i1] - lg[i0]));
    float w1 = 1.f - w0;

    int p0 = atomicAdd(&g_cnt[i0], 1);
    int item0 = bsmp * 2;
    g_list[i0 * BATCH + p0] = item0;
    g_gatew[item0] = w0;
    int p1 = atomicAdd(&g_cnt[i1], 1);
    int item1 = bsmp * 2 + 1;
    g_list[i1 * BATCH + p1] = item1;
    g_gatew[item1] = w1;
}

// ---------------- NT GEMM: 64x64 tile, FFMA2 (m-paired acc, duplicated W) --------
template <int MODE>
__global__ __launch_bounds__(256) void sgemm_nt(const float* __restrict__ W0,
                                                const float* __restrict__ bias0,
                                                float* __restrict__ C0,
                                                int N, int K) {
    const int e = blockIdx.z;
    const int m0 = blockIdx.x * 64, n0 = blockIdx.y * 64;
    const int Me = (MODE == 0) ? BATCH : g_cnt[e];
    if (m0 >= Me) return;
    const int* list = g_list + e * BATCH;
    const float* W = W0 + (size_t)e * N * K;
    const float* bias = bias0 + (size_t)e * N;

    __shared__ __align__(16) float As[16][68];
    __shared__ __align__(16) float Wd[16][140];   // duplicated: Wd[k][2n]=Wd[k][2n+1]=W[n][k]
    const int tid = threadIdx.x;
    const int lm = tid >> 2, lq = tid & 3;

    const float* arow = nullptr;
    bool mv = (m0 + lm) < Me;
    if (mv) {
        if (MODE == 0) arow = g_feat + (size_t)(m0 + lm) * K;
        else {
            int item = list[m0 + lm];
            arow = (MODE == 1) ? (g_feat + (size_t)(item >> 1) * K)
                 : (MODE == 2) ? (g_h1 + (size_t)item * K)
                               : (g_h2 + (size_t)item * K);
        }
    }
    bool nv = (n0 + lm) < N;
    const float* wrow = nv ? (W + (size_t)(n0 + lm) * K) : nullptr;

    const int tx = tid & 15, ty = tid >> 4;   // rows ty*4..+3, cols tx*4..+3
    unsigned long long acc2[2][4];            // acc2[i][j] = (C[r0+2i][c], C[r0+2i+1][c])
#pragma unroll
    for (int i = 0; i < 2; i++)
#pragma unroll
        for (int j = 0; j < 4; j++) acc2[i][j] = 0ull;

    const int ktn = K >> 4;
    for (int kt = 0; kt < ktn; kt++) {
        int k0 = (kt << 4) + (lq << 2);
        float4 av = mv ? *(const float4*)(arow + k0) : make_float4(0, 0, 0, 0);
        float4 wv = nv ? *(const float4*)(wrow + k0) : make_float4(0, 0, 0, 0);
        __syncthreads();
        As[lq * 4 + 0][lm] = av.x; As[lq * 4 + 1][lm] = av.y;
        As[lq * 4 + 2][lm] = av.z; As[lq * 4 + 3][lm] = av.w;
        *(float2*)&Wd[lq * 4 + 0][2 * lm] = make_float2(wv.x, wv.x);
        *(float2*)&Wd[lq * 4 + 1][2 * lm] = make_float2(wv.y, wv.y);
        *(float2*)&Wd[lq * 4 + 2][2 * lm] = make_float2(wv.z, wv.z);
        *(float2*)&Wd[lq * 4 + 3][2 * lm] = make_float2(wv.w, wv.w);
        __syncthreads();
#pragma unroll
        for (int kk = 0; kk < 16; kk++) {
            ulonglong2 ap = *(const ulonglong2*)&As[kk][ty << 2];
            ulonglong2 w01 = *(const ulonglong2*)&Wd[kk][tx << 3];
            ulonglong2 w23 = *(const ulonglong2*)&Wd[kk][(tx << 3) + 4];
            acc2[0][0] = fma2(ap.x, w01.x, acc2[0][0]);
            acc2[0][1] = fma2(ap.x, w01.y, acc2[0][1]);
            acc2[0][2] = fma2(ap.x, w23.x, acc2[0][2]);
            acc2[0][3] = fma2(ap.x, w23.y, acc2[0][3]);
            acc2[1][0] = fma2(ap.y, w01.x, acc2[1][0]);
            acc2[1][1] = fma2(ap.y, w01.y, acc2[1][1]);
            acc2[1][2] = fma2(ap.y, w23.x, acc2[1][2]);
            acc2[1][3] = fma2(ap.y, w23.y, acc2[1][3]);
        }
    }

#pragma unroll
    for (int i = 0; i < 2; i++) {
#pragma unroll
        for (int j = 0; j < 4; j++) {
            float vlo, vhi;
            unpack2(acc2[i][j], vlo, vhi);
            int nn = n0 + (tx << 2) + j;
            if (nn >= N) continue;
            float bv = bias[nn];
#pragma unroll
            for (int h = 0; h < 2; h++) {
                int m = m0 + (ty << 2) + 2 * i + h;
                if (m >= Me) continue;
                float v = (h ? vhi : vlo) + bv;
                int item = 0;
                if (MODE != 0) item = list[m];
                if (MODE == 0)      g_gh[(size_t)m * GH + nn] = fmaxf(v, 0.f);
                else if (MODE == 1) g_h1[(size_t)item * HID + nn] = fmaxf(v, 0.f);
                else if (MODE == 2) g_h2[(size_t)item * HID2 + nn] = fmaxf(v, 0.f);
                else atomicAdd(&C0[(size_t)(item >> 1) * NOUT + nn], g_gatew[item] * v);
            }
        }
    }
}

// ---------------- final log_softmax(|out|) ----------------
__global__ __launch_bounds__(256) void logsoftmax_kernel(float* __restrict__ out) {
    __shared__ float red[32];
    int b = blockIdx.x, tid = threadIdx.x;
    float* row = out + (size_t)b * NOUT;

    float m = -1e30f;
    for (int i = tid; i < NOUT; i += 256) m = fmaxf(m, fabsf(row[i]));
#pragma unroll
    for (int off = 16; off > 0; off >>= 1) m = fmaxf(m, __shfl_xor_sync(0xffffffffu, m, off));
    if ((tid & 31) == 0) red[tid >> 5] = m;
    __syncthreads();
    if (tid < 32) {
        float v = (tid < 8) ? red[tid] : -1e30f;
#pragma unroll
        for (int off = 4; off > 0; off >>= 1) v = fmaxf(v, __shfl_xor_sync(0xffffffffu, v, off));
        if (tid == 0) red[0] = v;
    }
    __syncthreads();
    m = red[0];
    __syncthreads();

    float s = 0.f;
    for (int i = tid; i < NOUT; i += 256) s += expf(fabsf(row[i]) - m);
#pragma unroll
    for (int off = 16; off > 0; off >>= 1) s += __shfl_xor_sync(0xffffffffu, s, off);
    if ((tid & 31) == 0) red[tid >> 5] = s;
    __syncthreads();
    if (tid < 32) {
        float v = (tid < 8) ? red[tid] : 0.f;
#pragma unroll
        for (int off = 4; off > 0; off >>= 1) v += __shfl_xor_sync(0xffffffffu, v, off);
        if (tid == 0) red[0] = v;
    }
    __syncthreads();
    float lse = m + logf(red[0]);
    for (int i = tid; i < NOUT; i += 256) row[i] = fabsf(row[i]) - lse;
}

// ---------------- launch ----------------
extern "C" void kernel_launch(void* const* d_in, const int* in_sizes, int n_in,
                              void* d_out, int out_size) {
    const float* x       = (const float*)d_in[0];
    const float* conv1_w = (const float*)d_in[1];
    const float* conv1_b = (const float*)d_in[2];
    const float* bn_g    = (const float*)d_in[3];
    const float* bn_b    = (const float*)d_in[4];
    const float* conv2_w = (const float*)d_in[5];
    const float* conv2_b = (const float*)d_in[6];
    const float* gate_w1 = (const float*)d_in[7];
    const float* gate_b1 = (const float*)d_in[8];
    const float* gate_w2 = (const float*)d_in[9];
    const float* gate_b2 = (const float*)d_in[10];
    const float* ew1     = (const float*)d_in[11];
    const float* eb1     = (const float*)d_in[12];
    const float* ew2     = (const float*)d_in[13];
    const float* eb2     = (const float*)d_in[14];
    const float* ew3     = (const float*)d_in[15];
    const float* eb3     = (const float*)d_in[16];
    float* out = (float*)d_out;

    cudaFuncSetAttribute(conv1_kernel, cudaFuncAttributeMaxDynamicSharedMemorySize, 61440);
    cudaFuncSetAttribute(conv2_kernel, cudaFuncAttributeMaxDynamicSharedMemorySize, 94208);

    init_kernel<<<1024, 256>>>(out);
    conv1_kernel<<<BATCH, 256, 59896>>>(x, conv1_w, conv1_b);
    bn_finalize<<<1, 32>>>(bn_g, bn_b);
    conv2_kernel<<<BATCH, 256, 92880>>>(conv2_w, conv2_b);
    sgemm_nt<0><<<dim3(64, 1, 1), 256>>>(gate_w1, gate_b1, nullptr, GH, FEAT);
    gate2_kernel<<<16, 256>>>(gate_w2, gate_b2);
    sgemm_nt<1><<<dim3(64, 2, NE), 256>>>(ew1, eb1, nullptr, HID, FEAT);
    sgemm_nt<2><<<dim3(64, 1, NE), 256>>>(ew2, eb2, nullptr, HID2, HID);
    sgemm_nt<3><<<dim3(64, 16, NE), 256>>>(ew3, eb3, out, NOUT, HID2);
    logsoftmax_kernel<<<BATCH, 256>>>(out);
}

// round 14
// speedup vs baseline: 1.2908x; 1.2908x over previous
#include <cuda_runtime.h>
#include <math.h>

#define BATCH 4096
#define C1O 10
#define P1 31
#define FEAT 3920
#define GH 64
#define NE 8
#define HID 128
#define HID2 64
#define NOUT 1000

// ---------------- scratch ----------------
__device__ float g_p1max[(size_t)BATCH * C1O * P1 * P1];
__device__ float g_p1min[(size_t)BATCH * C1O * P1 * P1];
__device__ float g_feat[(size_t)BATCH * FEAT];
__device__ float g_gh[(size_t)BATCH * GH];
__device__ float g_h1[(size_t)BATCH * 2 * HID];
__device__ float g_h2[(size_t)BATCH * 2 * HID2];
__device__ float g_gatew[BATCH * 2];
__device__ int   g_list[NE * BATCH];
__device__ int   g_cnt[NE];
__device__ double g_sum[C1O], g_sumsq[C1O];
__device__ float g_bnA[C1O], g_bnB[C1O];

// ---------------- f32x2 helpers ----------------
__device__ __forceinline__ unsigned long long pack2(float lo, float hi) {
    unsigned long long r;
    asm("mov.b64 %0, {%1, %2};" : "=l"(r) : "f"(lo), "f"(hi));
    return r;
}
__device__ __forceinline__ void unpack2(unsigned long long v, float& lo, float& hi) {
    asm("mov.b64 {%0, %1}, %2;" : "=f"(lo), "=f"(hi) : "l"(v));
}
__device__ __forceinline__ unsigned long long fma2(unsigned long long a,
                                                   unsigned long long b,
                                                   unsigned long long c) {
    unsigned long long d;
    asm("fma.rn.f32x2 %0, %1, %2, %3;" : "=l"(d) : "l"(a), "l"(b), "l"(c));
    return d;
}

// ---------------- init ----------------
__global__ void init_kernel(float* out) {
    size_t stride = (size_t)gridDim.x * blockDim.x;
    for (size_t i = (size_t)blockIdx.x * blockDim.x + threadIdx.x;
         i < (size_t)BATCH * NOUT; i += stride)
        out[i] = 0.f;
    if (blockIdx.x == 0 && threadIdx.x < 32) {
        if (threadIdx.x < NE) g_cnt[threadIdx.x] = 0;
        if (threadIdx.x < C1O) { g_sum[threadIdx.x] = 0.0; g_sumsq[threadIdx.x] = 0.0; }
    }
}

// ---------------- conv1 (3->10,5x5,p1): R6 two row-passes ----------
__global__ __launch_bounds__(256, 2) void conv1_kernel(const float* __restrict__ x,
                                                       const float* __restrict__ w,
                                                       const float* __restrict__ b) {
    extern __shared__ float sm[];
    float* pin = sm;                           // [3][66][68] = 13464
    float2* ws2 = (float2*)(sm + 13464);       // 750 duplicated weights
    float* bs = sm + 13464 + 1500;             // 10
    __shared__ float sh1[C1O], sh2[C1O];
    const int n = blockIdx.x, tid = threadIdx.x;

    if (tid < C1O) { sh1[tid] = 0.f; sh2[tid] = 0.f; bs[tid] = b[tid]; }
    for (int i = tid; i < 13464; i += 256) pin[i] = 0.f;
    for (int i = tid; i < 750; i += 256) { float wv = w[i]; ws2[i] = make_float2(wv, wv); }
    __syncthreads();
    const float* xn = x + (size_t)n * 3 * 64 * 64;
    for (int i = tid; i < 3 * 64 * 64; i += 256) {
        int c = i >> 12, r = (i >> 6) & 63, cc = i & 63;
        pin[(c * 66 + r + 1) * 68 + cc + 1] = xn[i];
    }
    __syncthreads();

    const bool valid = tid < 248;
    const int i = valid ? (tid >> 3) : 30;
    const int xg = (tid & 7) << 3;

#pragma unroll 1
    for (int grp = 0; grp < 2; grp++) {
        const int co0 = grp * 5;
        float cmx[5][4], cmn[5][4];
        float s1[5], s2[5];
#pragma unroll
        for (int co = 0; co < 5; co++) { s1[co] = 0.f; s2[co] = 0.f; }

#pragma unroll 1
        for (int pass = 0; pass < 2; pass++) {
            const int y = 2 * i + pass;
            unsigned long long acc[5][4];
#pragma unroll
            for (int co = 0; co < 5; co++) {
                float bb = bs[co0 + co];
                unsigned long long bp = pack2(bb, bb);
#pragma unroll
                for (int p = 0; p < 4; p++) acc[co][p] = bp;
            }
#pragma unroll 1
            for (int ci = 0; ci < 3; ci++) {
                const float* rb = &pin[(ci * 66 + y) * 68 + xg];
#pragma unroll
                for (int ky = 0; ky < 5; ky++) {
                    const float* rp = rb + ky * 68;
                    float4 q0 = *(const float4*)rp;
                    float4 q1 = *(const float4*)(rp + 4);
                    float4 q2 = *(const float4*)(rp + 8);
                    unsigned long long pe[6] = {
                        pack2(q0.x, q0.y), pack2(q0.z, q0.w), pack2(q1.x, q1.y),
                        pack2(q1.z, q1.w), pack2(q2.x, q2.y), pack2(q2.z, q2.w)};
                    unsigned long long po[5] = {
                        pack2(q0.y, q0.z), pack2(q0.w, q1.x), pack2(q1.y, q1.z),
                        pack2(q1.w, q2.x), pack2(q2.y, q2.z)};
#pragma unroll
                    for (int co = 0; co < 5; co++) {
                        const float2* wb = &ws2[((co0 + co) * 3 + ci) * 25 + ky * 5];
#pragma unroll
                        for (int kx = 0; kx < 5; kx++) {
                            unsigned long long w2 = *(const unsigned long long*)(wb + kx);
#pragma unroll
                            for (int p = 0; p < 4; p++) {
                                unsigned long long in = (kx & 1) ? po[p + (kx >> 1)]
                                                                 : pe[p + (kx >> 1)];
                                acc[co][p] = fma2(in, w2, acc[co][p]);
                            }
                        }
                    }
                }
            }
            // fold pass: stats + horizontal pool
#pragma unroll
            for (int co = 0; co < 5; co++) {
                float v[8];
#pragma unroll
                for (int p = 0; p < 4; p++) unpack2(acc[co][p], v[2 * p], v[2 * p + 1]);
                if (valid) {
#pragma unroll
                    for (int j = 0; j < 8; j++)
                        if (xg + j < 62) { float t = v[j]; s1[co] += t; s2[co] += t * t; }
                }
#pragma unroll
                for (int p = 0; p < 4; p++) {
                    float hx = fmaxf(v[2 * p], v[2 * p + 1]);
                    float hn = fminf(v[2 * p], v[2 * p + 1]);
                    if (pass == 0) { cmx[co][p] = hx; cmn[co][p] = hn; }
                    else { cmx[co][p] = fmaxf(cmx[co][p], hx); cmn[co][p] = fminf(cmn[co][p], hn); }
                }
            }
        }

        // stats reduce + pooled store
#pragma unroll
        for (int co = 0; co < 5; co++) {
            float a1 = s1[co], a2 = s2[co];
#pragma unroll
            for (int off = 16; off > 0; off >>= 1) {
                a1 += __shfl_down_sync(0xffffffffu, a1, off);
                a2 += __shfl_down_sync(0xffffffffu, a2, off);
            }
            if ((tid & 31) == 0) { atomicAdd(&sh1[co0 + co], a1); atomicAdd(&sh2[co0 + co], a2); }
            if (valid) {
                size_t ob = (((size_t)n * C1O + co0 + co) * P1 + i) * P1;
                int pc0 = xg >> 1;
#pragma unroll
                for (int p = 0; p < 4; p++) {
                    int pc = pc0 + p;
                    if (pc < P1) {
                        g_p1max[ob + pc] = cmx[co][p];
                        g_p1min[ob + pc] = cmn[co][p];
                    }
                }
            }
        }
    }
    __syncthreads();
    if (tid < C1O) {
        atomicAdd(&g_sum[tid], (double)sh1[tid]);
        atomicAdd(&g_sumsq[tid], (double)sh2[tid]);
    }
}

// ---------------- BN finalize ----------------
__global__ void bn_finalize(const float* __restrict__ gg, const float* __restrict__ gb) {
    int c = threadIdx.x;
    if (c < C1O) {
        double cnt = (double)BATCH * 62.0 * 62.0;
        double mean = g_sum[c] / cnt;
        double var = g_sumsq[c] / cnt - mean * mean;
        float istd = (float)(1.0 / sqrt(var + 1e-5));
        float a = gg[c] * istd;
        g_bnA[c] = a;
        g_bnB[c] = gb[c] - (float)mean * a;
    }
}

// ---------------- conv2 (10->20,5x5,p1): R6 two row-passes ----------
__global__ __launch_bounds__(256, 2) void conv2_kernel(const float* __restrict__ w,
                                                       const float* __restrict__ b) {
    extern __shared__ float sm[];
    float* pin = sm;                          // [10][33][40] = 13200
    float2* ws2 = (float2*)(sm + 13200);      // 5000
    float* bs = sm + 13200 + 10000;           // 20
    const int n = blockIdx.x, tid = threadIdx.x;

    for (int i = tid; i < 13200; i += 256) pin[i] = 0.f;
    for (int i = tid; i < 5000; i += 256) { float wv = w[i]; ws2[i] = make_float2(wv, wv); }
    if (tid < 20) bs[tid] = b[tid];
    __syncthreads();

    const float* pmaxn = g_p1max + (size_t)n * C1O * P1 * P1;
    const float* pminn = g_p1min + (size_t)n * C1O * P1 * P1;
    for (int idx = tid; idx < C1O * P1 * P1; idx += 256) {
        int c = idx / 961;
        int r = (idx - c * 961) / 31;
        int cc = idx - c * 961 - r * 31;
        float a = g_bnA[c];
        float v = (a >= 0.f) ? pmaxn[idx] : pminn[idx];
        pin[(c * 33 + r + 1) * 40 + cc + 1] = fmaxf(fmaf(a, v, g_bnB[c]), 0.f);
    }
    __syncthreads();

    const int grp = tid >> 6;
    const int rem = tid & 63;
    const bool act = rem < 56;
    const int i2 = act ? (rem >> 2) : 0;
    const int jg = rem & 3;
    const int co0 = grp * 5, c0 = jg * 8;

    float carry[5][4];
#pragma unroll 1
    for (int pass = 0; pass < 2; pass++) {
        const int y = 2 * i2 + pass;
        unsigned long long acc[5][4];
#pragma unroll
        for (int co = 0; co < 5; co++) {
            float bb = bs[co0 + co];
            unsigned long long bp = pack2(bb, bb);
#pragma unroll
            for (int p = 0; p < 4; p++) acc[co][p] = bp;
        }
#pragma unroll 1
        for (int ci = 0; ci < 10; ci++) {
            const float* rb = &pin[(ci * 33 + y) * 40 + c0];
#pragma unroll
            for (int ky = 0; ky < 5; ky++) {
                const float* rp = rb + ky * 40;
                float4 q0 = *(const float4*)rp;
                float4 q1 = *(const float4*)(rp + 4);
                float4 q2 = *(const float4*)(rp + 8);
                unsigned long long pe[6] = {
                    pack2(q0.x, q0.y), pack2(q0.z, q0.w), pack2(q1.x, q1.y),
                    pack2(q1.z, q1.w), pack2(q2.x, q2.y), pack2(q2.z, q2.w)};
                unsigned long long po[5] = {
                    pack2(q0.y, q0.z), pack2(q0.w, q1.x), pack2(q1.y, q1.z),
                    pack2(q1.w, q2.x), pack2(q2.y, q2.z)};
#pragma unroll
                for (int co = 0; co < 5; co++) {
                    const float2* wb = &ws2[((co0 + co) * 10 + ci) * 25 + ky * 5];
#pragma unroll
                    for (int kx = 0; kx < 5; kx++) {
                        unsigned long long w2 = *(const unsigned long long*)(wb + kx);
#pragma unroll
                        for (int p = 0; p < 4; p++) {
                            unsigned long long in = (kx & 1) ? po[p + (kx >> 1)]
                                                             : pe[p + (kx >> 1)];
                            acc[co][p] = fma2(in, w2, acc[co][p]);
                        }
                    }
                }
            }
        }
#pragma unroll
        for (int co = 0; co < 5; co++) {
#pragma unroll
            for (int p = 0; p < 4; p++) {
                float lo, hi;
                unpack2(acc[co][p], lo, hi);
                float h = fmaxf(lo, hi);
                if (pass == 0) carry[co][p] = h;
                else carry[co][p] = fmaxf(carry[co][p], h);
            }
        }
    }

    if (act) {
#pragma unroll
        for (int co = 0; co < 5; co++) {
            size_t ob = (size_t)n * FEAT + (co0 + co) * 196 + i2 * 14;
#pragma unroll
            for (int p = 0; p < 4; p++) {
                int oc = jg * 4 + p;
                if (oc < 14) g_feat[ob + oc] = fmaxf(carry[co][p], 0.f);
            }
        }
    }
}

// ---------------- gate layer 2 + top-2 + list build ----------------
__global__ __launch_bounds__(256) void gate2_kernel(const float* __restrict__ w2,
                                                    const float* __restrict__ b2) {
    __shared__ float ws[NE * GH], bs[NE];
    int tid = threadIdx.x;
    for (int i = tid; i < NE * GH; i += 256) ws[i] = w2[i];
    if (tid < NE) bs[tid] = b2[tid];
    __syncthreads();

    int bsmp = blockIdx.x * 256 + tid;
    if (bsmp >= BATCH) return;
    float h[GH];
    const float* row = g_gh + (size_t)bsmp * GH;
#pragma unroll
    for (int i = 0; i < GH; i++) h[i] = row[i];

    float lg[NE];
#pragma unroll
    for (int e = 0; e < NE; e++) {
        float s = bs[e];
        const float* wr = &ws[e * GH];
#pragma unroll
        for (int i = 0; i < GH; i++) s = fmaf(h[i], wr[i], s);
        lg[e] = s;
    }
    int i0 = 0;
#pragma unroll
    for (int e = 1; e < NE; e++) if (lg[e] > lg[i0]) i0 = e;
    int i1 = (i0 == 0) ? 1 : 0;
#pragma unroll
    for (int e = 0; e < NE; e++) if (e != i0 && lg[e] > lg[i1]) i1 = e;
    float w0 = 1.f / (1.f + expf(lg[i1] - lg[i0]));
    float w1 = 1.f - w0;

    int p0 = atomicAdd(&g_cnt[i0], 1);
    int item0 = bsmp * 2;
    g_list[i0 * BATCH + p0] = item0;
    g_gatew[item0] = w0;
    int p1 = atomicAdd(&g_cnt[i1], 1);
    int item1 = bsmp * 2 + 1;
    g_list[i1 * BATCH + p1] = item1;
    g_gatew[item1] = w1;
}

// ---------------- NT GEMM: 64x64, FFMA2 (duplicated-A broadcast, scalar W) -------
template <int MODE>
__global__ __launch_bounds__(256) void sgemm_nt(const float* __restrict__ W0,
                                                const float* __restrict__ bias0,
                                                float* __restrict__ C0,
                                                int N, int K) {
    const int e = blockIdx.z;
    const int m0 = blockIdx.x * 64, n0 = blockIdx.y * 64;
    const int Me = (MODE == 0) ? BATCH : g_cnt[e];
    if (m0 >= Me) return;
    const int* list = g_list + e * BATCH;
    const float* W = W0 + (size_t)e * N * K;
    const float* bias = bias0 + (size_t)e * N;

    __shared__ __align__(16) float Ad[16][140];   // dup pairs: Ad[k][2m]=Ad[k][2m+1]=A[m][k]
    __shared__ __align__(16) float Ws[16][68];
    const int tid = threadIdx.x;
    const int lm = tid >> 2, lq = tid & 3;

    const float* arow = nullptr;
    bool mv = (m0 + lm) < Me;
    if (mv) {
        if (MODE == 0) arow = g_feat + (size_t)(m0 + lm) * K;
        else {
            int item = list[m0 + lm];
            arow = (MODE == 1) ? (g_feat + (size_t)(item >> 1) * K)
                 : (MODE == 2) ? (g_h1 + (size_t)item * K)
                               : (g_h2 + (size_t)item * K);
        }
    }
    bool nv = (n0 + lm) < N;
    const float* wrow = nv ? (W + (size_t)(n0 + lm) * K) : nullptr;

    const int tx = tid & 15, ty = tid >> 4;   // rows ty*4..+3, cols tx*4..+3
    unsigned long long acc2[4][2];            // acc2[r][jp] = (C[m][c+2jp], C[m][c+2jp+1])
#pragma unroll
    for (int r = 0; r < 4; r++)
#pragma unroll
        for (int jp = 0; jp < 2; jp++) acc2[r][jp] = 0ull;

    const int ktn = K >> 4;
    for (int kt = 0; kt < ktn; kt++) {
        int k0 = (kt << 4) + (lq << 2);
        float4 av = mv ? *(const float4*)(arow + k0) : make_float4(0, 0, 0, 0);
        float4 wv = nv ? *(const float4*)(wrow + k0) : make_float4(0, 0, 0, 0);
        __syncthreads();
        *(float2*)&Ad[lq * 4 + 0][2 * lm] = make_float2(av.x, av.x);
        *(float2*)&Ad[lq * 4 + 1][2 * lm] = make_float2(av.y, av.y);
        *(float2*)&Ad[lq * 4 + 2][2 * lm] = make_float2(av.z, av.z);
        *(float2*)&Ad[lq * 4 + 3][2 * lm] = make_float2(av.w, av.w);
        Ws[lq * 4 + 0][lm] = wv.x; Ws[lq * 4 + 1][lm] = wv.y;
        Ws[lq * 4 + 2][lm] = wv.z; Ws[lq * 4 + 3][lm] = wv.w;
        __syncthreads();
#pragma unroll
        for (int kk = 0; kk < 16; kk++) {
            ulonglong2 a01 = *(const ulonglong2*)&Ad[kk][ty << 3];          // rows 0,1 dup
            ulonglong2 a23 = *(const ulonglong2*)&Ad[kk][(ty << 3) + 4];    // rows 2,3 dup
            ulonglong2 wp = *(const ulonglong2*)&Ws[kk][tx << 2];           // col pairs
            acc2[0][0] = fma2(a01.x, wp.x, acc2[0][0]);
            acc2[0][1] = fma2(a01.x, wp.y, acc2[0][1]);
            acc2[1][0] = fma2(a01.y, wp.x, acc2[1][0]);
            acc2[1][1] = fma2(a01.y, wp.y, acc2[1][1]);
            acc2[2][0] = fma2(a23.x, wp.x, acc2[2][0]);
            acc2[2][1] = fma2(a23.x, wp.y, acc2[2][1]);
            acc2[3][0] = fma2(a23.y, wp.x, acc2[3][0]);
            acc2[3][1] = fma2(a23.y, wp.y, acc2[3][1]);
        }
    }

#pragma unroll
    for (int r = 0; r < 4; r++) {
        int m = m0 + (ty << 2) + r;
        if (m >= Me) continue;
        int item = 0;
        if (MODE != 0) item = list[m];
#pragma unroll
        for (int jp = 0; jp < 2; jp++) {
            float vlo, vhi;
            unpack2(acc2[r][jp], vlo, vhi);
#pragma unroll
            for (int h = 0; h < 2; h++) {
                int nn = n0 + (tx << 2) + 2 * jp + h;
                if (nn >= N) continue;
                float v = (h ? vhi : vlo) + bias[nn];
                if (MODE == 0)      g_gh[(size_t)m * GH + nn] = fmaxf(v, 0.f);
                else if (MODE == 1) g_h1[(size_t)item * HID + nn] = fmaxf(v, 0.f);
                else if (MODE == 2) g_h2[(size_t)item * HID2 + nn] = fmaxf(v, 0.f);
                else atomicAdd(&C0[(size_t)(item >> 1) * NOUT + nn], g_gatew[item] * v);
            }
        }
    }
}

// ---------------- final log_softmax(|out|) ----------------
__global__ __launch_bounds__(256) void logsoftmax_kernel(float* __restrict__ out) {
    __shared__ float red[32];
    int b = blockIdx.x, tid = threadIdx.x;
    float* row = out + (size_t)b * NOUT;

    float m = -1e30f;
    for (int i = tid; i < NOUT; i += 256) m = fmaxf(m, fabsf(row[i]));
#pragma unroll
    for (int off = 16; off > 0; off >>= 1) m = fmaxf(m, __shfl_xor_sync(0xffffffffu, m, off));
    if ((tid & 31) == 0) red[tid >> 5] = m;
    __syncthreads();
    if (tid < 32) {
        float v = (tid < 8) ? red[tid] : -1e30f;
#pragma unroll
        for (int off = 4; off > 0; off >>= 1) v = fmaxf(v, __shfl_xor_sync(0xffffffffu, v, off));
        if (tid == 0) red[0] = v;
    }
    __syncthreads();
    m = red[0];
    __syncthreads();

    float s = 0.f;
    for (int i = tid; i < NOUT; i += 256) s += expf(fabsf(row[i]) - m);
#pragma unroll
    for (int off = 16; off > 0; off >>= 1) s += __shfl_xor_sync(0xffffffffu, s, off);
    if ((tid & 31) == 0) red[tid >> 5] = s;
    __syncthreads();
    if (tid < 32) {
        float v = (tid < 8) ? red[tid] : 0.f;
#pragma unroll
        for (int off = 4; off > 0; off >>= 1) v += __shfl_xor_sync(0xffffffffu, v, off);
        if (tid == 0) red[0] = v;
    }
    __syncthreads();
    float lse = m + logf(red[0]);
    for (int i = tid; i < NOUT; i += 256) row[i] = fabsf(row[i]) - lse;
}

// ---------------- launch ----------------
extern "C" void kernel_launch(void* const* d_in, const int* in_sizes, int n_in,
                              void* d_out, int out_size) {
    const float* x       = (const float*)d_in[0];
    const float* conv1_w = (const float*)d_in[1];
    const float* conv1_b = (const float*)d_in[2];
    const float* bn_g    = (const float*)d_in[3];
    const float* bn_b    = (const float*)d_in[4];
    const float* conv2_w = (const float*)d_in[5];
    const float* conv2_b = (const float*)d_in[6];
    const float* gate_w1 = (const float*)d_in[7];
    const float* gate_b1 = (const float*)d_in[8];
    const float* gate_w2 = (const float*)d_in[9];
    const float* gate_b2 = (const float*)d_in[10];
    const float* ew1     = (const float*)d_in[11];
    const float* eb1     = (const float*)d_in[12];
    const float* ew2     = (const float*)d_in[13];
    const float* eb2     = (const float*)d_in[14];
    const float* ew3     = (const float*)d_in[15];
    const float* eb3     = (const float*)d_in[16];
    float* out = (float*)d_out;

    cudaFuncSetAttribute(conv1_kernel, cudaFuncAttributeMaxDynamicSharedMemorySize, 61440);
    cudaFuncSetAttribute(conv2_kernel, cudaFuncAttributeMaxDynamicSharedMemorySize, 94208);

    init_kernel<<<1024, 256>>>(out);
    conv1_kernel<<<BATCH, 256, 59896>>>(x, conv1_w, conv1_b);
    bn_finalize<<<1, 32>>>(bn_g, bn_b);
    conv2_kernel<<<BATCH, 256, 92880>>>(conv2_w, conv2_b);
    sgemm_nt<0><<<dim3(64, 1, 1), 256>>>(gate_w1, gate_b1, nullptr, GH, FEAT);
    gate2_kernel<<<16, 256>>>(gate_w2, gate_b2);
    sgemm_nt<1><<<dim3(64, 2, NE), 256>>>(ew1, eb1, nullptr, HID, FEAT);
    sgemm_nt<2><<<dim3(64, 1, NE), 256>>>(ew2, eb2, nullptr, HID2, HID);
    sgemm_nt<3><<<dim3(64, 16, NE), 256>>>(ew3, eb3, out, NOUT, HID2);
    logsoftmax_kernel<<<BATCH, 256>>>(out);
}

// round 15
// speedup vs baseline: 1.3686x; 1.0603x over previous
#include <cuda_runtime.h>
#include <math.h>

#define BATCH 4096
#define C1O 10
#define P1 31
#define FEAT 3920
#define GH 64
#define NE 8
#define HID 128
#define HID2 64
#define NOUT 1000

// ---------------- scratch ----------------
__device__ float g_p1max[(size_t)BATCH * C1O * P1 * P1];
__device__ float g_p1min[(size_t)BATCH * C1O * P1 * P1];
__device__ float g_feat[(size_t)BATCH * FEAT];
__device__ float g_gh[(size_t)BATCH * GH];
__device__ float g_h1[(size_t)BATCH * 2 * HID];
__device__ float g_h2[(size_t)BATCH * 2 * HID2];
__device__ float g_gatew[BATCH * 2];
__device__ int   g_list[NE * BATCH];
__device__ int   g_cnt[NE];
__device__ double g_sum[C1O], g_sumsq[C1O];
__device__ float g_bnA[C1O], g_bnB[C1O];

// ---------------- f32x2 helpers ----------------
__device__ __forceinline__ unsigned long long pack2(float lo, float hi) {
    unsigned long long r;
    asm("mov.b64 %0, {%1, %2};" : "=l"(r) : "f"(lo), "f"(hi));
    return r;
}
__device__ __forceinline__ void unpack2(unsigned long long v, float& lo, float& hi) {
    asm("mov.b64 {%0, %1}, %2;" : "=f"(lo), "=f"(hi) : "l"(v));
}
__device__ __forceinline__ unsigned long long fma2(unsigned long long a,
                                                   unsigned long long b,
                                                   unsigned long long c) {
    unsigned long long d;
    asm("fma.rn.f32x2 %0, %1, %2, %3;" : "=l"(d) : "l"(a), "l"(b), "l"(c));
    return d;
}

// ---------------- init ----------------
__global__ void init_kernel(float* out) {
    size_t stride = (size_t)gridDim.x * blockDim.x;
    for (size_t i = (size_t)blockIdx.x * blockDim.x + threadIdx.x;
         i < (size_t)BATCH * NOUT; i += stride)
        out[i] = 0.f;
    if (blockIdx.x == 0 && threadIdx.x < 32) {
        if (threadIdx.x < NE) g_cnt[threadIdx.x] = 0;
        if (threadIdx.x < C1O) { g_sum[threadIdx.x] = 0.0; g_sumsq[threadIdx.x] = 0.0; }
    }
}

// ---------------- conv1 (3->10,5x5,p1): R6 two row-passes ----------
__global__ __launch_bounds__(256, 2) void conv1_kernel(const float* __restrict__ x,
                                                       const float* __restrict__ w,
                                                       const float* __restrict__ b) {
    extern __shared__ float sm[];
    float* pin = sm;                           // [3][66][68] = 13464
    float2* ws2 = (float2*)(sm + 13464);       // 750 duplicated weights
    float* bs = sm + 13464 + 1500;             // 10
    __shared__ float sh1[C1O], sh2[C1O];
    const int n = blockIdx.x, tid = threadIdx.x;

    if (tid < C1O) { sh1[tid] = 0.f; sh2[tid] = 0.f; bs[tid] = b[tid]; }
    for (int i = tid; i < 13464; i += 256) pin[i] = 0.f;
    for (int i = tid; i < 750; i += 256) { float wv = w[i]; ws2[i] = make_float2(wv, wv); }
    __syncthreads();
    const float* xn = x + (size_t)n * 3 * 64 * 64;
    for (int i = tid; i < 3 * 64 * 64; i += 256) {
        int c = i >> 12, r = (i >> 6) & 63, cc = i & 63;
        pin[(c * 66 + r + 1) * 68 + cc + 1] = xn[i];
    }
    __syncthreads();

    const bool valid = tid < 248;
    const int i = valid ? (tid >> 3) : 30;
    const int xg = (tid & 7) << 3;

#pragma unroll 1
    for (int grp = 0; grp < 2; grp++) {
        const int co0 = grp * 5;
        float cmx[5][4], cmn[5][4];
        float s1[5], s2[5];
#pragma unroll
        for (int co = 0; co < 5; co++) { s1[co] = 0.f; s2[co] = 0.f; }

#pragma unroll 1
        for (int pass = 0; pass < 2; pass++) {
            const int y = 2 * i + pass;
            unsigned long long acc[5][4];
#pragma unroll
            for (int co = 0; co < 5; co++) {
                float bb = bs[co0 + co];
                unsigned long long bp = pack2(bb, bb);
#pragma unroll
                for (int p = 0; p < 4; p++) acc[co][p] = bp;
            }
#pragma unroll 1
            for (int ci = 0; ci < 3; ci++) {
                const float* rb = &pin[(ci * 66 + y) * 68 + xg];
#pragma unroll
                for (int ky = 0; ky < 5; ky++) {
                    const float* rp = rb + ky * 68;
                    float4 q0 = *(const float4*)rp;
                    float4 q1 = *(const float4*)(rp + 4);
                    float4 q2 = *(const float4*)(rp + 8);
                    unsigned long long pe[6] = {
                        pack2(q0.x, q0.y), pack2(q0.z, q0.w), pack2(q1.x, q1.y),
                        pack2(q1.z, q1.w), pack2(q2.x, q2.y), pack2(q2.z, q2.w)};
                    unsigned long long po[5] = {
                        pack2(q0.y, q0.z), pack2(q0.w, q1.x), pack2(q1.y, q1.z),
                        pack2(q1.w, q2.x), pack2(q2.y, q2.z)};
#pragma unroll
                    for (int co = 0; co < 5; co++) {
                        const float2* wb = &ws2[((co0 + co) * 3 + ci) * 25 + ky * 5];
#pragma unroll
                        for (int kx = 0; kx < 5; kx++) {
                            unsigned long long w2 = *(const unsigned long long*)(wb + kx);
#pragma unroll
                            for (int p = 0; p < 4; p++) {
                                unsigned long long in = (kx & 1) ? po[p + (kx >> 1)]
                                                                 : pe[p + (kx >> 1)];
                                acc[co][p] = fma2(in, w2, acc[co][p]);
                            }
                        }
                    }
                }
            }
            // fold pass: stats + horizontal pool
#pragma unroll
            for (int co = 0; co < 5; co++) {
                float v[8];
#pragma unroll
                for (int p = 0; p < 4; p++) unpack2(acc[co][p], v[2 * p], v[2 * p + 1]);
                if (valid) {
#pragma unroll
                    for (int j = 0; j < 8; j++)
                        if (xg + j < 62) { float t = v[j]; s1[co] += t; s2[co] += t * t; }
                }
#pragma unroll
                for (int p = 0; p < 4; p++) {
                    float hx = fmaxf(v[2 * p], v[2 * p + 1]);
                    float hn = fminf(v[2 * p], v[2 * p + 1]);
                    if (pass == 0) { cmx[co][p] = hx; cmn[co][p] = hn; }
                    else { cmx[co][p] = fmaxf(cmx[co][p], hx); cmn[co][p] = fminf(cmn[co][p], hn); }
                }
            }
        }

        // stats reduce + pooled store
#pragma unroll
        for (int co = 0; co < 5; co++) {
            float a1 = s1[co], a2 = s2[co];
#pragma unroll
            for (int off = 16; off > 0; off >>= 1) {
                a1 += __shfl_down_sync(0xffffffffu, a1, off);
                a2 += __shfl_down_sync(0xffffffffu, a2, off);
            }
            if ((tid & 31) == 0) { atomicAdd(&sh1[co0 + co], a1); atomicAdd(&sh2[co0 + co], a2); }
            if (valid) {
                size_t ob = (((size_t)n * C1O + co0 + co) * P1 + i) * P1;
                int pc0 = xg >> 1;
#pragma unroll
                for (int p = 0; p < 4; p++) {
                    int pc = pc0 + p;
                    if (pc < P1) {
                        g_p1max[ob + pc] = cmx[co][p];
                        g_p1min[ob + pc] = cmn[co][p];
                    }
                }
            }
        }
    }
    __syncthreads();
    if (tid < C1O) {
        atomicAdd(&g_sum[tid], (double)sh1[tid]);
        atomicAdd(&g_sumsq[tid], (double)sh2[tid]);
    }
}

// ---------------- BN finalize ----------------
__global__ void bn_finalize(const float* __restrict__ gg, const float* __restrict__ gb) {
    int c = threadIdx.x;
    if (c < C1O) {
        double cnt = (double)BATCH * 62.0 * 62.0;
        double mean = g_sum[c] / cnt;
        double var = g_sumsq[c] / cnt - mean * mean;
        float istd = (float)(1.0 / sqrt(var + 1e-5));
        float a = gg[c] * istd;
        g_bnA[c] = a;
        g_bnB[c] = gb[c] - (float)mean * a;
    }
}

// ---------------- conv2 (10->20,5x5,p1): R6 + ci unroll 2 ----------
__global__ __launch_bounds__(256, 2) void conv2_kernel(const float* __restrict__ w,
                                                       const float* __restrict__ b) {
    extern __shared__ float sm[];
    float* pin = sm;                          // [10][33][40] = 13200
    float2* ws2 = (float2*)(sm + 13200);      // 5000
    float* bs = sm + 13200 + 10000;           // 20
    const int n = blockIdx.x, tid = threadIdx.x;

    for (int i = tid; i < 13200; i += 256) pin[i] = 0.f;
    for (int i = tid; i < 5000; i += 256) { float wv = w[i]; ws2[i] = make_float2(wv, wv); }
    if (tid < 20) bs[tid] = b[tid];
    __syncthreads();

    const float* pmaxn = g_p1max + (size_t)n * C1O * P1 * P1;
    const float* pminn = g_p1min + (size_t)n * C1O * P1 * P1;
    for (int idx = tid; idx < C1O * P1 * P1; idx += 256) {
        int c = idx / 961;
        int r = (idx - c * 961) / 31;
        int cc = idx - c * 961 - r * 31;
        float a = g_bnA[c];
        float v = (a >= 0.f) ? pmaxn[idx] : pminn[idx];
        pin[(c * 33 + r + 1) * 40 + cc + 1] = fmaxf(fmaf(a, v, g_bnB[c]), 0.f);
    }
    __syncthreads();

    const int grp = tid >> 6;
    const int rem = tid & 63;
    const bool act = rem < 56;
    const int i2 = act ? (rem >> 2) : 0;
    const int jg = rem & 3;
    const int co0 = grp * 5, c0 = jg * 8;

    float carry[5][4];
#pragma unroll 1
    for (int pass = 0; pass < 2; pass++) {
        const int y = 2 * i2 + pass;
        unsigned long long acc[5][4];
#pragma unroll
        for (int co = 0; co < 5; co++) {
            float bb = bs[co0 + co];
            unsigned long long bp = pack2(bb, bb);
#pragma unroll
            for (int p = 0; p < 4; p++) acc[co][p] = bp;
        }
#pragma unroll 2
        for (int ci = 0; ci < 10; ci++) {
            const float* rb = &pin[(ci * 33 + y) * 40 + c0];
#pragma unroll
            for (int ky = 0; ky < 5; ky++) {
                const float* rp = rb + ky * 40;
                float4 q0 = *(const float4*)rp;
                float4 q1 = *(const float4*)(rp + 4);
                float4 q2 = *(const float4*)(rp + 8);
                unsigned long long pe[6] = {
                    pack2(q0.x, q0.y), pack2(q0.z, q0.w), pack2(q1.x, q1.y),
                    pack2(q1.z, q1.w), pack2(q2.x, q2.y), pack2(q2.z, q2.w)};
                unsigned long long po[5] = {
                    pack2(q0.y, q0.z), pack2(q0.w, q1.x), pack2(q1.y, q1.z),
                    pack2(q1.w, q2.x), pack2(q2.y, q2.z)};
#pragma unroll
                for (int co = 0; co < 5; co++) {
                    const float2* wb = &ws2[((co0 + co) * 10 + ci) * 25 + ky * 5];
#pragma unroll
                    for (int kx = 0; kx < 5; kx++) {
                        unsigned long long w2 = *(const unsigned long long*)(wb + kx);
#pragma unroll
                        for (int p = 0; p < 4; p++) {
                            unsigned long long in = (kx & 1) ? po[p + (kx >> 1)]
                                                             : pe[p + (kx >> 1)];
                            acc[co][p] = fma2(in, w2, acc[co][p]);
                        }
                    }
                }
            }
        }
#pragma unroll
        for (int co = 0; co < 5; co++) {
#pragma unroll
            for (int p = 0; p < 4; p++) {
                float lo, hi;
                unpack2(acc[co][p], lo, hi);
                float h = fmaxf(lo, hi);
                if (pass == 0) carry[co][p] = h;
                else carry[co][p] = fmaxf(carry[co][p], h);
            }
        }
    }

    if (act) {
#pragma unroll
        for (int co = 0; co < 5; co++) {
            size_t ob = (size_t)n * FEAT + (co0 + co) * 196 + i2 * 14;
#pragma unroll
            for (int p = 0; p < 4; p++) {
                int oc = jg * 4 + p;
                if (oc < 14) g_feat[ob + oc] = fmaxf(carry[co][p], 0.f);
            }
        }
    }
}

// ---------------- gate layer 2 + top-2 + list build ----------------
__global__ __launch_bounds__(256) void gate2_kernel(const float* __restrict__ w2,
                                                    const float* __restrict__ b2) {
    __shared__ float ws[NE * GH], bs[NE];
    int tid = threadIdx.x;
    for (int i = tid; i < NE * GH; i += 256) ws[i] = w2[i];
    if (tid < NE) bs[tid] = b2[tid];
    __syncthreads();

    int bsmp = blockIdx.x * 256 + tid;
    if (bsmp >= BATCH) return;
    float h[GH];
    const float* row = g_gh + (size_t)bsmp * GH;
#pragma unroll
    for (int i = 0; i < GH; i++) h[i] = row[i];

    float lg[NE];
#pragma unroll
    for (int e = 0; e < NE; e++) {
        float s = bs[e];
        const float* wr = &ws[e * GH];
#pragma unroll
        for (int i = 0; i < GH; i++) s = fmaf(h[i], wr[i], s);
        lg[e] = s;
    }
    int i0 = 0;
#pragma unroll
    for (int e = 1; e < NE; e++) if (lg[e] > lg[i0]) i0 = e;
    int i1 = (i0 == 0) ? 1 : 0;
#pragma unroll
    for (int e = 0; e < NE; e++) if (e != i0 && lg[e] > lg[i1]) i1 = e;
    float w0 = 1.f / (1.f + expf(lg[i1] - lg[i0]));
    float w1 = 1.f - w0;

    int p0 = atomicAdd(&g_cnt[i0], 1);
    int item0 = bsmp * 2;
    g_list[i0 * BATCH + p0] = item0;
    g_gatew[item0] = w0;
    int p1 = atomicAdd(&g_cnt[i1], 1);
    int item1 = bsmp * 2 + 1;
    g_list[i1 * BATCH + p1] = item1;
    g_gatew[item1] = w1;
}

// ---------------- NT GEMM: 64x64 tile, 4x4/thread (R6 scalar config) ----------------
template <int MODE>
__global__ __launch_bounds__(256) void sgemm_nt(const float* __restrict__ W0,
                                                const float* __restrict__ bias0,
                                                float* __restrict__ C0,
                                                int N, int K) {
    const int e = blockIdx.z;
    const int m0 = blockIdx.x * 64, n0 = blockIdx.y * 64;
    const int Me = (MODE == 0) ? BATCH : g_cnt[e];
    if (m0 >= Me) return;
    const int* list = g_list + e * BATCH;
    const float* W = W0 + (size_t)e * N * K;
    const float* bias = bias0 + (size_t)e * N;

    __shared__ __align__(16) float As[16][68], Ws[16][68];
    const int tid = threadIdx.x;
    const int lm = tid >> 2, lq = tid & 3;

    const float* arow = nullptr;
    bool mv = (m0 + lm) < Me;
    if (mv) {
        if (MODE == 0) arow = g_feat + (size_t)(m0 + lm) * K;
        else {
            int item = list[m0 + lm];
            arow = (MODE == 1) ? (g_feat + (size_t)(item >> 1) * K)
                 : (MODE == 2) ? (g_h1 + (size_t)item * K)
                               : (g_h2 + (size_t)item * K);
        }
    }
    bool nv = (n0 + lm) < N;
    const float* wrow = nv ? (W + (size_t)(n0 + lm) * K) : nullptr;

    const int tx = tid & 15, ty = tid >> 4;
    float acc[4][4];
#pragma unroll
    for (int i = 0; i < 4; i++)
#pragma unroll
        for (int j = 0; j < 4; j++) acc[i][j] = 0.f;

    const int ktn = K >> 4;
    for (int kt = 0; kt < ktn; kt++) {
        int k0 = (kt << 4) + (lq << 2);
        float4 av = mv ? *(const float4*)(arow + k0) : make_float4(0, 0, 0, 0);
        float4 wv = nv ? *(const float4*)(wrow + k0) : make_float4(0, 0, 0, 0);
        __syncthreads();
        As[lq * 4 + 0][lm] = av.x; As[lq * 4 + 1][lm] = av.y;
        As[lq * 4 + 2][lm] = av.z; As[lq * 4 + 3][lm] = av.w;
        Ws[lq * 4 + 0][lm] = wv.x; Ws[lq * 4 + 1][lm] = wv.y;
        Ws[lq * 4 + 2][lm] = wv.z; Ws[lq * 4 + 3][lm] = wv.w;
        __syncthreads();
#pragma unroll
        for (int kk = 0; kk < 16; kk++) {
            float4 a4 = *(const float4*)&As[kk][ty << 2];
            float4 w4 = *(const float4*)&Ws[kk][tx << 2];
            float aa[4] = {a4.x, a4.y, a4.z, a4.w};
            float ww[4] = {w4.x, w4.y, w4.z, w4.w};
#pragma unroll
            for (int i = 0; i < 4; i++)
#pragma unroll
                for (int j = 0; j < 4; j++) acc[i][j] = fmaf(aa[i], ww[j], acc[i][j]);
        }
    }

#pragma unroll
    for (int i = 0; i < 4; i++) {
        int m = m0 + (ty << 2) + i;
        if (m >= Me) continue;
        int item = 0;
        if (MODE != 0) item = list[m];
#pragma unroll
        for (int j = 0; j < 4; j++) {
            int nn = n0 + (tx << 2) + j;
            if (nn >= N) continue;
            float v = acc[i][j] + bias[nn];
            if (MODE == 0)      g_gh[(size_t)m * GH + nn] = fmaxf(v, 0.f);
            else if (MODE == 1) g_h1[(size_t)item * HID + nn] = fmaxf(v, 0.f);
            else if (MODE == 2) g_h2[(size_t)item * HID2 + nn] = fmaxf(v, 0.f);
            else atomicAdd(&C0[(size_t)(item >> 1) * NOUT + nn], g_gatew[item] * v);
        }
    }
}

// ---------------- final log_softmax(|out|) ----------------
__global__ __launch_bounds__(256) void logsoftmax_kernel(float* __restrict__ out) {
    __shared__ float red[32];
    int b = blockIdx.x, tid = threadIdx.x;
    float* row = out + (size_t)b * NOUT;

    float m = -1e30f;
    for (int i = tid; i < NOUT; i += 256) m = fmaxf(m, fabsf(row[i]));
#pragma unroll
    for (int off = 16; off > 0; off >>= 1) m = fmaxf(m, __shfl_xor_sync(0xffffffffu, m, off));
    if ((tid & 31) == 0) red[tid >> 5] = m;
    __syncthreads();
    if (tid < 32) {
        float v = (tid < 8) ? red[tid] : -1e30f;
#pragma unroll
        for (int off = 4; off > 0; off >>= 1) v = fmaxf(v, __shfl_xor_sync(0xffffffffu, v, off));
        if (tid == 0) red[0] = v;
    }
    __syncthreads();
    m = red[0];
    __syncthreads();

    float s = 0.f;
    for (int i = tid; i < NOUT; i += 256) s += expf(fabsf(row[i]) - m);
#pragma unroll
    for (int off = 16; off > 0; off >>= 1) s += __shfl_xor_sync(0xffffffffu, s, off);
    if ((tid & 31) == 0) red[tid >> 5] = s;
    __syncthreads();
    if (tid < 32) {
        float v = (tid < 8) ? red[tid] : 0.f;
#pragma unroll
        for (int off = 4; off > 0; off >>= 1) v += __shfl_xor_sync(0xffffffffu, v, off);
        if (tid == 0) red[0] = v;
    }
    __syncthreads();
    float lse = m + logf(red[0]);
    for (int i = tid; i < NOUT; i += 256) row[i] = fabsf(row[i]) - lse;
}

// ---------------- launch ----------------
extern "C" void kernel_launch(void* const* d_in, const int* in_sizes, int n_in,
                              void* d_out, int out_size) {
    const float* x       = (const float*)d_in[0];
    const float* conv1_w = (const float*)d_in[1];
    const float* conv1_b = (const float*)d_in[2];
    const float* bn_g    = (const float*)d_in[3];
    const float* bn_b    = (const float*)d_in[4];
    const float* conv2_w = (const float*)d_in[5];
    const float* conv2_b = (const float*)d_in[6];
    const float* gate_w1 = (const float*)d_in[7];
    const float* gate_b1 = (const float*)d_in[8];
    const float* gate_w2 = (const float*)d_in[9];
    const float* gate_b2 = (const float*)d_in[10];
    const float* ew1     = (const float*)d_in[11];
    const float* eb1     = (const float*)d_in[12];
    const float* ew2     = (const float*)d_in[13];
    const float* eb2     = (const float*)d_in[14];
    const float* ew3     = (const float*)d_in[15];
    const float* eb3     = (const float*)d_in[16];
    float* out = (float*)d_out;

    cudaFuncSetAttribute(conv1_kernel, cudaFuncAttributeMaxDynamicSharedMemorySize, 61440);
    cudaFuncSetAttribute(conv2_kernel, cudaFuncAttributeMaxDynamicSharedMemorySize, 94208);

    init_kernel<<<1024, 256>>>(out);
    conv1_kernel<<<BATCH, 256, 59896>>>(x, conv1_w, conv1_b);
    bn_finalize<<<1, 32>>>(bn_g, bn_b);
    conv2_kernel<<<BATCH, 256, 92880>>>(conv2_w, conv2_b);
    sgemm_nt<0><<<dim3(64, 1, 1), 256>>>(gate_w1, gate_b1, nullptr, GH, FEAT);
    gate2_kernel<<<16, 256>>>(gate_w2, gate_b2);
    sgemm_nt<1><<<dim3(64, 2, NE), 256>>>(ew1, eb1, nullptr, HID, FEAT);
    sgemm_nt<2><<<dim3(64, 1, NE), 256>>>(ew2, eb2, nullptr, HID2, HID);
    sgemm_nt<3><<<dim3(64, 16, NE), 256>>>(ew3, eb3, out, NOUT, HID2);
    logsoftmax_kernel<<<BATCH, 256>>>(out);
}